// round 3
// baseline (speedup 1.0000x reference)
#include <cuda_runtime.h>

// Problem constants
#define NROWS   1024
#define REPD    256
#define NPIX    32768      // 8 * 64 * 64
#define LOG2E_F   1.4426950408889634f
#define LOG_2PI_F 1.8378770664093453f
#define EPS_F     1e-6f

__device__ __forceinline__ float ex2f(float x) {
    float y;
    asm("ex2.approx.ftz.f32 %0, %1;" : "=f"(y) : "f"(x));
    return y;
}

// numerically stable softplus (used only ~12x per block, accuracy-first)
__device__ __forceinline__ float softplusf(float x) {
    return fmaxf(x, 0.0f) + log1pf(expf(-fabsf(x)));
}

__global__ __launch_bounds__(256) void mvn_profile_kernel(
    const float* __restrict__ rep,     // [1024,256]
    const float* __restrict__ meanW,   // [3,256]
    const float* __restrict__ meanb,   // [3]
    const float* __restrict__ scaleW,  // [6,256]
    const float* __restrict__ scaleb,  // [6]
    float* __restrict__ out)           // [1024,32768]
{
    extern __shared__ float4 cache4[];   // 8192 float4 = 32768 floats = 128KB
    __shared__ float red[8][9];
    __shared__ float dots[9];
    __shared__ float wS[8];
    __shared__ float s_invS;

    const int row  = blockIdx.x;
    const int t    = threadIdx.x;
    const int warp = t >> 5;
    const int lane = t & 31;

    // ---- Phase 1: 9 dot products (3 means + 6 raw scales) ----
    float r = rep[row * REPD + t];
    float p[9];
#pragma unroll
    for (int k = 0; k < 3; k++) p[k]     = r * meanW[k * REPD + t];
#pragma unroll
    for (int k = 0; k < 6; k++) p[3 + k] = r * scaleW[k * REPD + t];

#pragma unroll
    for (int k = 0; k < 9; k++) {
        float v = p[k];
#pragma unroll
        for (int o = 16; o; o >>= 1) v += __shfl_xor_sync(0xffffffffu, v, o);
        if (lane == 0) red[warp][k] = v;
    }
    __syncthreads();
    if (t < 9) {
        float s = (t < 3) ? meanb[t] : scaleb[t - 3];
#pragma unroll
        for (int w = 0; w < 8; w++) s += red[w][t];
        dots[t] = s;
    }
    __syncthreads();

    // ---- Phase 2: quadratic-form coefficients (redundant per thread) ----
    const float mx = dots[0], my = dots[1], mz = dots[2];
    const float s0 = softplusf(dots[3]) + EPS_F;
    const float s1 = softplusf(dots[4]) + EPS_F;
    const float s2 = softplusf(dots[5]) + EPS_F;
    const float s3 = softplusf(dots[6]) + EPS_F;
    const float s4 = softplusf(dots[7]) + EPS_F;
    const float s5 = softplusf(dots[8]) + EPS_F;

    const float L00 = softplusf(s0);
    const float L10 = s1;
    const float L11 = softplusf(s2);
    const float L20 = s3;
    const float L21 = s4;
    const float L22 = softplusf(s5);

    const float a = 1.0f / L00, b = 1.0f / L11, c = 1.0f / L22;
    const float m10 = -L10 * a * b;
    const float m21 = -L21 * b * c;
    const float m20 = -c * (L20 * a + L21 * m10);
    const float Qxx = a * a + m10 * m10 + m20 * m20;
    const float Qyy = b * b + m21 * m21;
    const float Qzz = c * c;
    const float Qxy = 2.0f * (m10 * b + m20 * m21);
    const float Qxz = 2.0f * (m20 * c);
    const float Qyz = 2.0f * (m21 * c);

    const float al  = -0.5f * LOG2E_F;   // fold -0.5 and base-2 conversion
    const float qxx = al * Qxx, qyy = al * Qyy, qzz = al * Qzz;
    const float qxy = al * Qxy, qxz = al * Qxz, qyz = al * Qyz;

    const float logdet = logf(L00) + logf(L11) + logf(L22);
    // No max pass: lp_max = -logdet - 1.5*log2pi is in [-5.6,-1.7] for these
    // scales, so exp(lp) itself is fp32-safe; normalization cancels the offset.
    const float K = LOG2E_F * (-logdet - 1.5f * LOG_2PI_F);

    // pixel index p = 1024*i + 4*t  ->  x-index = 4*(t&15)+j, scanline = 16*i + (t>>4)
    const float x0  = 4.0f * (float)(t & 15) - 31.5f;
    const float dx0 = x0 - mx, dx1 = dx0 + 1.0f, dx2 = dx0 + 2.0f, dx3 = dx0 + 3.0f;
    const float h0 = qxx * dx0, h1 = qxx * dx1, h2 = qxx * dx2, h3 = qxx * dx3;
    const int rbase = t >> 4;
    const float dy_base = (float)rbase - 31.5f - my;

    // ---- Phase A: compute exp(lp), cache in smem, accumulate sum ----
    float S0 = 0.0f, S1 = 0.0f, S2 = 0.0f, S3 = 0.0f;
#pragma unroll
    for (int z = 0; z < 8; z++) {
        const float dz    = (float)z - 3.5f - mz;
        const float qxzdz = qxz * dz;
        const float qyzdz = qyz * dz;
        const float Cz    = fmaf(qzz * dz, dz, K);
        float dy = dy_base;
#pragma unroll
        for (int k = 0; k < 4; k++) {
            const float B0 = fmaf(qxy, dy, qxzdz);
            const float C0 = fmaf(dy, fmaf(qyy, dy, qyzdz), Cz);
            float4 v;
            v.x = ex2f(fmaf(dx0, h0 + B0, C0));
            v.y = ex2f(fmaf(dx1, h1 + B0, C0));
            v.z = ex2f(fmaf(dx2, h2 + B0, C0));
            v.w = ex2f(fmaf(dx3, h3 + B0, C0));
            cache4[(z * 4 + k) * 256 + t] = v;
            S0 += v.x; S1 += v.y; S2 += v.z; S3 += v.w;
            dy += 16.0f;
        }
    }
    float S = (S0 + S1) + (S2 + S3);
#pragma unroll
    for (int o = 16; o; o >>= 1) S += __shfl_xor_sync(0xffffffffu, S, o);
    if (lane == 0) wS[warp] = S;
    __syncthreads();
    if (t == 0) {
        float SS = wS[0];
#pragma unroll
        for (int w = 1; w < 8; w++) SS += wS[w];
        s_invS = 1.0f / (SS + 1e-10f);
    }
    __syncthreads();
    const float invS = s_invS;

    // ---- Phase B: normalize from smem cache, streaming float4 stores ----
    float4* __restrict__ out4 = (float4*)(out + (size_t)row * NPIX);
#pragma unroll 8
    for (int i = 0; i < 32; i++) {
        float4 v = cache4[i * 256 + t];
        v.x *= invS; v.y *= invS; v.z *= invS; v.w *= invS;
        __stcs(&out4[i * 256 + t], v);   // evict-first: output >> L2
    }
}

extern "C" void kernel_launch(void* const* d_in, const int* in_sizes, int n_in,
                              void* d_out, int out_size) {
    const float* rep    = (const float*)d_in[0];
    const float* meanW  = (const float*)d_in[1];
    const float* meanb  = (const float*)d_in[2];
    const float* scaleW = (const float*)d_in[3];
    const float* scaleb = (const float*)d_in[4];
    float* out = (float*)d_out;

    const int smem_bytes = NPIX * (int)sizeof(float);   // 128 KB dynamic smem
    cudaFuncSetAttribute(mvn_profile_kernel,
                         cudaFuncAttributeMaxDynamicSharedMemorySize, smem_bytes);
    mvn_profile_kernel<<<NROWS, 256, smem_bytes>>>(rep, meanW, meanb, scaleW, scaleb, out);
}

// round 5
// speedup vs baseline: 1.3139x; 1.3139x over previous
#include <cuda_runtime.h>

// Problem constants
#define NROWS   1024
#define REPD    256
#define NPIX    32768      // 8 * 64 * 64
#define LOG2E_F   1.4426950408889634f
#define LOG_2PI_F 1.8378770664093453f
#define EPS_F     1e-6f

__device__ __forceinline__ float ex2f(float x) {
    float y;
    asm("ex2.approx.ftz.f32 %0, %1;" : "=f"(y) : "f"(x));
    return y;
}

// numerically stable softplus (used only ~12x per block, accuracy-first)
__device__ __forceinline__ float softplusf(float x) {
    return fmaxf(x, 0.0f) + log1pf(expf(-fabsf(x)));
}

__global__ __launch_bounds__(256) void mvn_profile_kernel(
    const float* __restrict__ rep,     // [1024,256]
    const float* __restrict__ meanW,   // [3,256]
    const float* __restrict__ meanb,   // [3]
    const float* __restrict__ scaleW,  // [6,256]
    const float* __restrict__ scaleb,  // [6]
    float* __restrict__ out)           // [1024,32768]
{
    __shared__ float red[8][9];
    __shared__ float dots[9];
    __shared__ float wS[8];
    __shared__ float s_invLogS;   // -log2(S + 1e-10)

    const int row  = blockIdx.x;
    const int t    = threadIdx.x;
    const int warp = t >> 5;
    const int lane = t & 31;

    // ---- Phase 1: 9 dot products (3 means + 6 raw scales) ----
    float r = rep[row * REPD + t];
    float p[9];
#pragma unroll
    for (int k = 0; k < 3; k++) p[k]     = r * meanW[k * REPD + t];
#pragma unroll
    for (int k = 0; k < 6; k++) p[3 + k] = r * scaleW[k * REPD + t];

#pragma unroll
    for (int k = 0; k < 9; k++) {
        float v = p[k];
#pragma unroll
        for (int o = 16; o; o >>= 1) v += __shfl_xor_sync(0xffffffffu, v, o);
        if (lane == 0) red[warp][k] = v;
    }
    __syncthreads();
    if (t < 9) {
        float s = (t < 3) ? meanb[t] : scaleb[t - 3];
#pragma unroll
        for (int w = 0; w < 8; w++) s += red[w][t];
        dots[t] = s;
    }
    __syncthreads();

    // ---- Phase 2: quadratic-form coefficients (redundant per thread) ----
    const float mx = dots[0], my = dots[1], mz = dots[2];
    const float s0 = softplusf(dots[3]) + EPS_F;
    const float s1 = softplusf(dots[4]) + EPS_F;
    const float s2 = softplusf(dots[5]) + EPS_F;
    const float s3 = softplusf(dots[6]) + EPS_F;
    const float s4 = softplusf(dots[7]) + EPS_F;
    const float s5 = softplusf(dots[8]) + EPS_F;

    const float L00 = softplusf(s0);
    const float L10 = s1;
    const float L11 = softplusf(s2);
    const float L20 = s3;
    const float L21 = s4;
    const float L22 = softplusf(s5);

    const float a = 1.0f / L00, b = 1.0f / L11, c = 1.0f / L22;
    const float m10 = -L10 * a * b;
    const float m21 = -L21 * b * c;
    const float m20 = -c * (L20 * a + L21 * m10);
    const float Qxx = a * a + m10 * m10 + m20 * m20;
    const float Qyy = b * b + m21 * m21;
    const float Qzz = c * c;
    const float Qxy = 2.0f * (m10 * b + m20 * m21);
    const float Qxz = 2.0f * (m20 * c);
    const float Qyz = 2.0f * (m21 * c);

    const float al  = -0.5f * LOG2E_F;   // fold -0.5 and base-2 conversion
    const float qxx = al * Qxx, qyy = al * Qyy, qzz = al * Qzz;
    const float qxy = al * Qxy, qxz = al * Qxz, qyz = al * Qyz;
    const float vtx = -0.25f / qxx;      // parabola vertex factor (qxx < 0)

    const float logdet = logf(L00) + logf(L11) + logf(L22);
    // No max pass: lp_max = -logdet - 1.5*log2pi is in a safe fp32 band for
    // these scales; normalization cancels the stability offset exactly.
    const float K = LOG2E_F * (-logdet - 1.5f * LOG_2PI_F);

    // pixel index p = 1024*i + 4*t  ->  x-index = 4*(t&15)+j, scanline = 16*i + (t>>4)
    const float x0  = 4.0f * (float)(t & 15) - 31.5f;
    const float dx0 = x0 - mx, dx1 = dx0 + 1.0f, dx2 = dx0 + 2.0f, dx3 = dx0 + 3.0f;
    const float h0 = qxx * dx0, h1 = qxx * dx1, h2 = qxx * dx2, h3 = qxx * dx3;
    const int   rbase   = t >> 4;
    const float dy_base = (float)rbase - 31.5f - my;

    // ---- Sweep A: sum of exp2(u); skip scanlines whose parabola vertex ----
    // ---- falls below the FTZ threshold (all grid values flush to 0).    ----
    float S = 0.0f;
#pragma unroll 4
    for (int i = 0; i < 32; i++) {
        const int   rowid = i * 16 + rbase;
        const float dy = dy_base + (float)(rowid & 48);   // (rowid&63)-31.5-my
        const float dz = (float)(rowid >> 6) - 3.5f - mz;
        const float B0 = fmaf(qxy, dy, qxz * dz);
        const float C0 = fmaf(dy, fmaf(qyy, dy, qyz * dz), fmaf(qzz * dz, dz, K));
        const float umax = fmaf(vtx * B0, B0, C0);        // C0 - B0^2/(4 qxx)
        if (__any_sync(0xffffffffu, umax > -124.0f)) {
            S += ex2f(fmaf(dx0, h0 + B0, C0))
               + ex2f(fmaf(dx1, h1 + B0, C0))
               + ex2f(fmaf(dx2, h2 + B0, C0))
               + ex2f(fmaf(dx3, h3 + B0, C0));
        }
    }
#pragma unroll
    for (int o = 16; o; o >>= 1) S += __shfl_xor_sync(0xffffffffu, S, o);
    if (lane == 0) wS[warp] = S;
    __syncthreads();
    if (t == 0) {
        float SS = wS[0];
#pragma unroll
        for (int w = 1; w < 8; w++) SS += wS[w];
        s_invLogS = -__log2f(SS + 1e-10f);
    }
    __syncthreads();

    // Final exponent offset: u - log2(sum)
    const float K2 = K + s_invLogS;

    // ---- Sweep B: write normalized profile; dead scanlines -> zero stores ----
    float4* __restrict__ out4 = (float4*)(out + (size_t)row * NPIX);
#pragma unroll 4
    for (int i = 0; i < 32; i++) {
        const int   rowid = i * 16 + rbase;
        const float dy = dy_base + (float)(rowid & 48);
        const float dz = (float)(rowid >> 6) - 3.5f - mz;
        const float B0 = fmaf(qxy, dy, qxz * dz);
        const float C0 = fmaf(dy, fmaf(qyy, dy, qyz * dz), fmaf(qzz * dz, dz, K2));
        const float umax = fmaf(vtx * B0, B0, C0);
        float4 v;
        if (__any_sync(0xffffffffu, umax > -124.0f)) {
            v.x = ex2f(fmaf(dx0, h0 + B0, C0));
            v.y = ex2f(fmaf(dx1, h1 + B0, C0));
            v.z = ex2f(fmaf(dx2, h2 + B0, C0));
            v.w = ex2f(fmaf(dx3, h3 + B0, C0));
        } else {
            v.x = 0.0f; v.y = 0.0f; v.z = 0.0f; v.w = 0.0f;
        }
        __stcs(&out4[i * 256 + t], v);   // evict-first: output >> L2
    }
}

extern "C" void kernel_launch(void* const* d_in, const int* in_sizes, int n_in,
                              void* d_out, int out_size) {
    const float* rep    = (const float*)d_in[0];
    const float* meanW  = (const float*)d_in[1];
    const float* meanb  = (const float*)d_in[2];
    const float* scaleW = (const float*)d_in[3];
    const float* scaleb = (const float*)d_in[4];
    float* out = (float*)d_out;

    mvn_profile_kernel<<<NROWS, 256>>>(rep, meanW, meanb, scaleW, scaleb, out);
}